// round 12
// baseline (speedup 1.0000x reference)
#include <cuda_runtime.h>
#include <math.h>

#define NN 100000
#define NE 1600000

// ---------------- static scratch (no allocations allowed) ----------------
__device__ int   g_row[NE];
__device__ int   g_col[NE];
__device__ int   g_cnt[NN];
__device__ int   g_ptr[NN + 1];
__device__ int   g_fill[NN];
__device__ int   g_src[NE];
__device__ int   g_csum[256];
__device__ int   g_is64;
__device__ __align__(16) float g_enorm[NE];
__device__ __align__(16) float g_dis[NN];
__device__ __align__(16) float g_ha[(size_t)NN * 128];
__device__ __align__(16) float g_hb[(size_t)NN * 128];
__device__ __align__(16) float g_o1[(size_t)NN * 128];
__device__ __align__(16) float g_o2[(size_t)NN * 64];

// internal buffer IDs: 0=g_ha 1=g_hb 2=g_o1 3=g_o2
__device__ __forceinline__ float* devbuf(int id) {
    switch (id) {
        case 0: return g_ha;
        case 1: return g_hb;
        case 2: return g_o1;
        default: return g_o2;
    }
}

// ---------------- JAX threefry2x32 (partitionable convention) ----------------
__host__ __device__ __forceinline__ unsigned rotl32(unsigned x, int r) {
    return (x << r) | (x >> (32 - r));
}

__host__ __device__ inline void threefry2x32(unsigned k0, unsigned k1,
                                             unsigned x0, unsigned x1,
                                             unsigned& o0, unsigned& o1) {
    unsigned ks0 = k0, ks1 = k1, ks2 = k0 ^ k1 ^ 0x1BD11BDAu;
    x0 += ks0; x1 += ks1;
#define TF_R(r) { x0 += x1; x1 = rotl32(x1, (r)); x1 ^= x0; }
    TF_R(13) TF_R(15) TF_R(26) TF_R(6)   x0 += ks1; x1 += ks2 + 1u;
    TF_R(17) TF_R(29) TF_R(16) TF_R(24)  x0 += ks2; x1 += ks0 + 2u;
    TF_R(13) TF_R(15) TF_R(26) TF_R(6)   x0 += ks0; x1 += ks1 + 3u;
    TF_R(17) TF_R(29) TF_R(16) TF_R(24)  x0 += ks1; x1 += ks2 + 4u;
    TF_R(13) TF_R(15) TF_R(26) TF_R(6)   x0 += ks2; x1 += ks0 + 5u;
#undef TF_R
    o0 = x0; o1 = x1;
}

// ---------------- graph prep ----------------
__global__ void zero_cnt_kernel() {
    int i = blockIdx.x * blockDim.x + threadIdx.x;
    if (i < NN) g_cnt[i] = 0;
}

// dtype probe: if edge_index is int64 (values < 2^31), every odd 32-bit word is 0
__global__ void detect_kernel(const int* ei32) {
    if (blockIdx.x == 0 && threadIdx.x == 0) {
        int zeros = 0;
        for (int i = 1; i < 64; i += 2) zeros += (ei32[i] == 0);
        g_is64 = (zeros == 32) ? 1 : 0;
    }
}

__global__ void prep_edges(const void* eiv) {
    int e = blockIdx.x * blockDim.x + threadIdx.x;
    if (e >= NE) return;
    int r, c;
    if (g_is64) {
        const long long* ei = (const long long*)eiv;
        r = (int)ei[e];
        c = (int)ei[NE + e];
    } else {
        const int* ei = (const int*)eiv;
        r = ei[e];
        c = ei[NE + e];
    }
    if ((unsigned)r < NN && (unsigned)c < NN) {
        g_row[e] = r;
        g_col[e] = c;
        atomicAdd(&g_cnt[c], 1);
    } else {
        g_row[e] = -1;   // invalid edge: drop
        g_col[e] = 0;
    }
}

// hierarchical exclusive scan of g_cnt into g_ptr via global memory only
__global__ void scanA_kernel() {
    int t = blockIdx.x * blockDim.x + threadIdx.x;
    if (t >= 250) return;
    int base = t * 400;
    int s = 0;
    for (int i = 0; i < 400; i++) s += g_cnt[base + i];
    g_csum[t] = s;
}

__global__ void scanB_kernel() {
    if (blockIdx.x == 0 && threadIdx.x == 0) {
        int run = 0;
        for (int i = 0; i < 250; i++) {
            int v = g_csum[i];
            g_csum[i] = run;
            run += v;
        }
        g_ptr[NN] = run;
    }
}

__global__ void scanC_kernel() {
    int t = blockIdx.x * blockDim.x + threadIdx.x;
    if (t >= 250) return;
    int base = t * 400;
    int run = g_csum[t];
    for (int i = 0; i < 400; i++) {
        g_ptr[base + i] = run;
        run += g_cnt[base + i];
    }
}

__global__ void dis_fill_kernel() {
    int i = blockIdx.x * blockDim.x + threadIdx.x;
    if (i >= NN) return;
    int c = g_cnt[i];
    g_dis[i] = (c > 0) ? (1.0f / sqrtf((float)c)) : 0.0f;
    g_fill[i] = g_ptr[i];
}

__global__ void fill_csr_kernel() {
    int e = blockIdx.x * blockDim.x + threadIdx.x;
    if (e >= NE) return;
    int r = g_row[e];
    if (r < 0) return;                 // dropped invalid edge
    int c = g_col[e];
    int p = atomicAdd(&g_fill[c], 1);
    g_src[p] = r;
    g_enorm[p] = g_dis[r] * g_dis[c];
}

// ---------------- propagation hop: out[c] = sum_e norm[e] * h[src[e]] ----------------
template <int D>
__global__ void prop_kernel(const float* hin_ext, int hin_id, int hout_id) {
    const float* __restrict__ hin = hin_ext ? hin_ext : devbuf(hin_id);
    float* __restrict__ hout = devbuf(hout_id);
    int w = blockIdx.x * (blockDim.x >> 5) + (threadIdx.x >> 5);
    if (w >= NN) return;
    int lane = threadIdx.x & 31;
    int s = g_ptr[w], e = g_ptr[w + 1];
    if (D == 128) {
        float4 acc = make_float4(0.f, 0.f, 0.f, 0.f);
        for (int i = s; i < e; i++) {
            int r = g_src[i];
            float wt = g_enorm[i];
            float4 v = *reinterpret_cast<const float4*>(hin + (size_t)r * 128 + lane * 4);
            acc.x += wt * v.x; acc.y += wt * v.y; acc.z += wt * v.z; acc.w += wt * v.w;
        }
        *reinterpret_cast<float4*>(hout + (size_t)w * 128 + lane * 4) = acc;
    } else {
        float2 acc = make_float2(0.f, 0.f);
        for (int i = s; i < e; i++) {
            int r = g_src[i];
            float wt = g_enorm[i];
            float2 v = *reinterpret_cast<const float2*>(hin + (size_t)r * 64 + lane * 2);
            acc.x += wt * v.x; acc.y += wt * v.y;
        }
        *reinterpret_cast<float2*>(hout + (size_t)w * 64 + lane * 2) = acc;
    }
}

// ---------------- GEMM: out[n,o] (+)= sum_d X[n,d] * W[o,d]  (+ bias on first) ----------
// Static shared memory (<= 25 KB), K-chunked tiles.
template <int NOUT, int KD, bool ACC>
__global__ void gemm_nt(const float* X_ext, int X_id,
                        const float* __restrict__ W, const float* __restrict__ bias,
                        float* out_ext, int out_id) {
    constexpr int BM = 64;
    constexpr int BK = 32;
    constexpr int TM = 4;
    constexpr int TN = NOUT / 16;
    constexpr int LDA = BK + 1;           // 33, conflict-free
    constexpr int LDW = NOUT + 1;         // odd, conflict-free

    __shared__ float As[BM * LDA];
    __shared__ float Ws[BK * LDW];

    const float* __restrict__ X = X_ext ? X_ext : devbuf(X_id);
    float* __restrict__ out = out_ext ? out_ext : devbuf(out_id);

    const int tx = threadIdx.x;           // 0..15
    const int ty = threadIdx.y;           // 0..15
    const int tid = ty * 16 + tx;
    const int m0 = blockIdx.x * BM;

    float acc[TM][TN];
#pragma unroll
    for (int i = 0; i < TM; i++)
#pragma unroll
        for (int j = 0; j < TN; j++) acc[i][j] = 0.f;

    for (int kc = 0; kc < KD; kc += BK) {
        for (int idx = tid; idx < BM * BK; idx += 256) {
            int m = idx >> 5, d = idx & 31;
            int node = m0 + m;
            As[m * LDA + d] = (node < NN) ? X[(size_t)node * KD + kc + d] : 0.0f;
        }
        for (int idx = tid; idx < NOUT * BK; idx += 256) {
            int o = idx >> 5, d = idx & 31;
            Ws[d * LDW + o] = W[(size_t)o * KD + kc + d];
        }
        __syncthreads();

#pragma unroll
        for (int d = 0; d < BK; d++) {
            float a[TM], b[TN];
#pragma unroll
            for (int i = 0; i < TM; i++) a[i] = As[(ty * TM + i) * LDA + d];
#pragma unroll
            for (int j = 0; j < TN; j++) b[j] = Ws[d * LDW + j * 16 + tx];
#pragma unroll
            for (int i = 0; i < TM; i++)
#pragma unroll
                for (int j = 0; j < TN; j++) acc[i][j] += a[i] * b[j];
        }
        __syncthreads();
    }

#pragma unroll
    for (int i = 0; i < TM; i++) {
        int node = m0 + ty * TM + i;
        if (node < NN) {
            float* po = out + (size_t)node * NOUT;
#pragma unroll
            for (int j = 0; j < TN; j++) {
                int o = j * 16 + tx;
                if (ACC) {
                    po[o] += acc[i][j];
                } else {
                    po[o] = acc[i][j] + bias[o];
                }
            }
        }
    }
}

// ---------------- dropout (+ optional ELU before it) ----------------
template <bool ELU>
__global__ void post_kernel(int buf_id, int n, unsigned k0, unsigned k1) {
    float* __restrict__ h = devbuf(buf_id);
    int i = blockIdx.x * blockDim.x + threadIdx.x;
    if (i >= n) return;
    float v = h[i];
    if (ELU) v = (v > 0.f) ? v : expm1f(v);
    unsigned o0, o1;
    threefry2x32(k0, k1, 0u, (unsigned)i, o0, o1);
    unsigned bits = o0 ^ o1;   // partitionable 32-bit combine
    h[i] = (bits & 0x80000000u) ? 0.f : 2.0f * v;
}

// ---------------- host orchestration: kernel launches ONLY ----------------
extern "C" void kernel_launch(void* const* d_in, const int* in_sizes, int n_in,
                              void* d_out, int out_size) {
    const float* x  = (const float*)d_in[0];
    const void*  ei = (const void*)d_in[1];
    const float* W1 = (const float*)d_in[2];
    const float* b1 = (const float*)d_in[3];
    const float* W2 = (const float*)d_in[4];
    const float* b2 = (const float*)d_in[5];
    const float* W3 = (const float*)d_in[6];
    const float* b3 = (const float*)d_in[7];
    float* out = (float*)d_out;

    // dropout keys: split(key(42)) under partitionable = threefry((0,42),(0,j))
    unsigned d10, d11, d20, d21;
    threefry2x32(0u, 42u, 0u, 0u, d10, d11);
    threefry2x32(0u, 42u, 0u, 1u, d20, d21);

    // graph prep
    zero_cnt_kernel<<<(NN + 255) / 256, 256>>>();
    detect_kernel<<<1, 32>>>((const int*)ei);
    prep_edges<<<(NE + 255) / 256, 256>>>(ei);
    scanA_kernel<<<1, 256>>>();
    scanB_kernel<<<1, 32>>>();
    scanC_kernel<<<1, 256>>>();
    dis_fill_kernel<<<(NN + 255) / 256, 256>>>();
    fill_csr_kernel<<<(NE + 255) / 256, 256>>>();

    dim3 gb(16, 16);
    const int ggrid = (NN + 63) / 64;
    const int pgrid = (NN + 7) / 8;        // 8 warps / 256-thread block

    // ---- layer 1: 128 -> 128 -> o1(id2) ----
    gemm_nt<128, 128, false><<<ggrid, gb>>>(x, -1, W1, b1, nullptr, 2);
    {
        const float* hp_ext = x; int hp_id = -1;
        int ht = 0;
        for (int k = 1; k <= 3; k++) {
            prop_kernel<128><<<pgrid, 256>>>(hp_ext, hp_id, ht);
            gemm_nt<128, 128, true><<<ggrid, gb>>>(nullptr, ht, W1 + (size_t)k * 128 * 128, nullptr, nullptr, 2);
            hp_ext = nullptr; hp_id = ht;
            ht ^= 1;
        }
    }
    post_kernel<false><<<(NN * 128 + 255) / 256, 256>>>(2, NN * 128, d10, d11);

    // ---- layer 2: 128 -> 64 -> o2(id3) ----
    gemm_nt<64, 128, false><<<ggrid, gb>>>(nullptr, 2, W2, b2, nullptr, 3);
    {
        int hp_id = 2;
        int ht = 0;
        for (int k = 1; k <= 3; k++) {
            prop_kernel<128><<<pgrid, 256>>>(nullptr, hp_id, ht);
            gemm_nt<64, 128, true><<<ggrid, gb>>>(nullptr, ht, W2 + (size_t)k * 64 * 128, nullptr, nullptr, 3);
            hp_id = ht;
            ht ^= 1;
        }
    }
    post_kernel<true><<<(NN * 64 + 255) / 256, 256>>>(3, NN * 64, d20, d21);

    // ---- layer 3: 64 -> 16 -> out (external) ----
    gemm_nt<16, 64, false><<<ggrid, gb>>>(nullptr, 3, W3, b3, out, -1);
    {
        int hp_id = 3;
        int ht = 0;
        for (int k = 1; k <= 3; k++) {
            prop_kernel<64><<<pgrid, 256>>>(nullptr, hp_id, ht);
            gemm_nt<16, 64, true><<<ggrid, gb>>>(nullptr, ht, W3 + (size_t)k * 16 * 64, nullptr, out, -1);
            hp_id = ht;
            ht ^= 1;
        }
    }
}